// round 8
// baseline (speedup 1.0000x reference)
#include <cuda_runtime.h>
#include <math.h>

#define BB 2
#define DIMC 96
#define INNER 192
#define NH 48
#define DH 4
#define SS 576
#define GTOT (BB*SS)   // 1152
#define F3 (3*INNER)   // 576
#define NBH (BB*NH)    // 96

// Scratch (device globals; no allocation allowed)
__device__ float g_z[GTOT * INNER];         // z half of up-proj
__device__ float g_xconv[GTOT * INNER];     // silu(causal conv)
__device__ float4 g_q4[NBH * SS];           // head-major q
__device__ float4 g_k4[NBH * SS];           // head-major k
__device__ float4 g_v4[NBH * SS];           // head-major v
__device__ float g_ig[NBH * SS];
__device__ float g_fg[NBH * SS];
__device__ float g_hnorm[GTOT * INNER];
// transposed / composed weights
__device__ float g_wupT[DIMC * 2 * INNER];  // [c][o]  96 x 384
__device__ float g_wcgT[384 * 96];          // composed gates: [f][j], f<192 xc-basis, f>=192 xm-basis
__device__ float g_bg[96];                  // composed gate bias (incl. bq/bk/bv effect)
__device__ float g_wdT[INNER * DIMC];       // [f][c]  192 x 96

// ---------------------------------------------------------------------------
// kT: weight transposes + gate-weight composition
//   ig_j = xc . W̃A[j] + xm . W̃B[j] + b̃_j   (same for fg rows j>=48)
//   W̃A[j][4n+d] = sum_o wg[j][4n+o] Wq[n][o][d] + wg[j][192+4n+o] Wk[n][o][d]
//   W̃B[j][4n+d] = sum_o wg[j][384+4n+o] Wv[n][o][d]
//   b̃_j = b_gate[j] + sum_o wg[j][o] bq[o] + wg[j][192+o] bk[o] + wg[j][384+o] bv[o]
// ---------------------------------------------------------------------------
__global__ void kT(const float* __restrict__ w_up,
                   const float* __restrict__ w_q, const float* __restrict__ b_q,
                   const float* __restrict__ w_k, const float* __restrict__ b_k,
                   const float* __restrict__ w_v, const float* __restrict__ b_v,
                   const float* __restrict__ w_ig, const float* __restrict__ b_ig,
                   const float* __restrict__ w_fg, const float* __restrict__ b_fg,
                   const float* __restrict__ w_down) {
    int i = blockIdx.x * 256 + threadIdx.x;
    if (i < DIMC * 384) {                       // 36864: wupT
        int c = i / 384, o = i % 384;
        g_wupT[c * 384 + o] = w_up[o * DIMC + c];
        return;
    }
    i -= DIMC * 384;
    if (i < 384 * 96) {                          // 36864: composed gate weights
        int f = i / 96, j = i % 96;
        const float* wg = (j < NH) ? (w_ig + j * F3) : (w_fg + (j - NH) * F3);
        float acc = 0.f;
        if (f < 192) {
            int n = f >> 2, d = f & 3;
#pragma unroll
            for (int o = 0; o < 4; o++) {
                acc += wg[4 * n + o]       * w_q[n * 16 + o * 4 + d];
                acc += wg[192 + 4 * n + o] * w_k[n * 16 + o * 4 + d];
            }
        } else {
            int fm = f - 192;
            int n = fm >> 2, d = fm & 3;
#pragma unroll
            for (int o = 0; o < 4; o++)
                acc += wg[384 + 4 * n + o] * w_v[n * 16 + o * 4 + d];
        }
        g_wcgT[f * 96 + j] = acc;
        return;
    }
    i -= 384 * 96;
    if (i < INNER * DIMC) {                      // 18432: wdT
        int f = i / DIMC, c = i % DIMC;
        g_wdT[f * DIMC + c] = w_down[c * INNER + f];
        return;
    }
    i -= INNER * DIMC;
    if (i < 96) {                                // 96: composed gate bias
        int j = i;
        const float* wg = (j < NH) ? (w_ig + j * F3) : (w_fg + (j - NH) * F3);
        float acc = (j < NH) ? b_ig[j] : b_fg[j - NH];
        for (int o = 0; o < 192; o++) {
            acc += wg[o] * b_q[o];
            acc += wg[192 + o] * b_k[o];
            acc += wg[384 + o] * b_v[o];
        }
        g_bg[j] = acc;
    }
}

// ---------------------------------------------------------------------------
// K_A: LN + up-proj (4 main + 3 halo rows for x_mlstm) + causal conv + SiLU +
// per-head qkv + composed gate pre-activations. 288 blocks x 384 threads.
// ---------------------------------------------------------------------------
__global__ void kA(const float* __restrict__ x,
                   const float* __restrict__ ln_g,
                   const float* __restrict__ ln_b,
                   const float* __restrict__ b_up,
                   const float* __restrict__ w_conv,
                   const float* __restrict__ b_conv,
                   const float* __restrict__ w_q, const float* __restrict__ b_q,
                   const float* __restrict__ w_k, const float* __restrict__ b_k,
                   const float* __restrict__ w_v, const float* __restrict__ b_v) {
    __shared__ __align__(16) float h[7][100];       // LN'd input (7 rows)
    __shared__ float mu[7], iv[7];
    __shared__ __align__(16) float xim[7][INNER];   // x_mlstm half
    __shared__ __align__(16) float xcv[4][INNER];   // silu(conv) per main position
    __shared__ __align__(16) float part[4][4][100]; // gate split-K partials
    const int g0 = blockIdx.x * 4;
    const int b = g0 / SS, sl0 = g0 % SS;   // blocks never straddle batches
    const int tid = threadIdx.x;            // 384
    const int wid = tid >> 5, lane = tid & 31;

    // ---- load x (7 rows: sloc = sl0-3+hp), zero-invalid
    for (int i = tid; i < 7 * DIMC; i += 384) {
        int hp = i / DIMC, c = i % DIMC;
        int sloc = sl0 - 3 + hp;
        h[hp][c] = (sloc >= 0) ? x[(b * DIMC + c) * SS + sloc] : 0.f;
    }
    __syncthreads();
    // ---- LN stats, warp per row
    if (wid < 7) {
        float sum = 0.f, sqv = 0.f;
        for (int c = lane; c < DIMC; c += 32) { float v = h[wid][c]; sum += v; sqv += v * v; }
#pragma unroll
        for (int off = 16; off > 0; off >>= 1) {
            sum += __shfl_down_sync(0xffffffffu, sum, off);
            sqv += __shfl_down_sync(0xffffffffu, sqv, off);
        }
        if (lane == 0) {
            float m = sum * (1.f / DIMC);
            float var = sqv * (1.f / DIMC) - m * m;
            mu[wid] = m;
            iv[wid] = rsqrtf(var + 1e-5f);
        }
    }
    __syncthreads();
    for (int i = tid; i < 7 * DIMC; i += 384) {
        int hp = i / DIMC, c = i % DIMC;
        h[hp][c] = (h[hp][c] - mu[hp]) * iv[hp] * ln_g[c] + ln_b[c];
    }
    __syncthreads();

    // ---- up-proj (coalesced transposed weights)
    if (tid < INNER) {
        const int o = tid;
        float acc[7];
        float bias = b_up[o];
#pragma unroll
        for (int p = 0; p < 7; p++) acc[p] = bias;
        for (int c = 0; c < DIMC; c++) {
            float w = g_wupT[c * 384 + o];
#pragma unroll
            for (int p = 0; p < 7; p++) acc[p] += w * h[p][c];
        }
#pragma unroll
        for (int p = 0; p < 7; p++) xim[p][o] = acc[p];
    } else {
        const int o = tid;                   // 192..383 -> z channels
        float acc[4];
        float bias = b_up[o];
#pragma unroll
        for (int p = 0; p < 4; p++) acc[p] = bias;
        for (int c = 0; c < DIMC; c++) {
            float w = g_wupT[c * 384 + o];
#pragma unroll
            for (int p = 0; p < 4; p++) acc[p] += w * h[p + 3][c];
        }
#pragma unroll
        for (int p = 0; p < 4; p++)
            g_z[(g0 + p) * INNER + (o - INNER)] = acc[p];
    }
    __syncthreads();

    // ---- conv + SiLU + qkv: thread = (p, n), 4*48 = 192 active
    if (tid < 192) {
        const int p = tid / NH, n = tid % NH;
        float xc[4];
#pragma unroll
        for (int d = 0; d < 4; d++) xc[d] = b_conv[n * 4 + d];
#pragma unroll
        for (int k = 0; k < 4; k++) {
            if (sl0 + p - 3 + k >= 0) {
                const float* xr = &xim[p + k][n * 4];
#pragma unroll
                for (int d = 0; d < 4; d++)
                    xc[d] += w_conv[(n * 4 + d) * 4 + k] * xr[d];
            }
        }
#pragma unroll
        for (int d = 0; d < 4; d++) {
            float sg = 1.f / (1.f + __expf(-xc[d]));
            xc[d] *= sg;
        }
        float xm0 = xim[p + 3][n * 4], xm1 = xim[p + 3][n * 4 + 1];
        float xm2 = xim[p + 3][n * 4 + 2], xm3 = xim[p + 3][n * 4 + 3];

        float4 xcf = make_float4(xc[0], xc[1], xc[2], xc[3]);
        *(float4*)(&xcv[p][n * 4]) = xcf;
        *(float4*)(g_xconv + (g0 + p) * INNER + n * 4) = xcf;

        float q[4], kk[4], v[4];
#pragma unroll
        for (int o = 0; o < 4; o++) {
            const float* wq = w_q + n * 16 + o * 4;
            q[o] = b_q[n * 4 + o] + wq[0] * xc[0] + wq[1] * xc[1] + wq[2] * xc[2] + wq[3] * xc[3];
            const float* wk = w_k + n * 16 + o * 4;
            kk[o] = b_k[n * 4 + o] + wk[0] * xc[0] + wk[1] * xc[1] + wk[2] * xc[2] + wk[3] * xc[3];
            const float* wv = w_v + n * 16 + o * 4;
            v[o] = b_v[n * 4 + o] + wv[0] * xm0 + wv[1] * xm1 + wv[2] * xm2 + wv[3] * xm3;
        }
        int hidx = (b * NH + n) * SS + sl0 + p;
        g_q4[hidx] = make_float4(q[0], q[1], q[2], q[3]);
        g_k4[hidx] = make_float4(kk[0], kk[1], kk[2], kk[3]);
        g_v4[hidx] = make_float4(v[0], v[1], v[2], v[3]);
    }
    __syncthreads();

    // ---- gates (composed basis): 96 rows x 4 f-slices of 96
    // slices 0,1 read xcv; slices 2,3 read xim[p+3]
    {
        const int r = tid % 96;
        const int slice = tid / 96;
        const int f0 = slice * 96;
        const float* actbase = (slice < 2) ? &xcv[0][f0] : &xim[3][f0 - 192];
        float acc[4];
#pragma unroll
        for (int p = 0; p < 4; p++) acc[p] = 0.f;
        for (int f = 0; f < 96; f++) {
            float w = g_wcgT[(f0 + f) * 96 + r];
#pragma unroll
            for (int p = 0; p < 4; p++) acc[p] += w * actbase[p * INNER + f];
        }
#pragma unroll
        for (int p = 0; p < 4; p++) part[p][slice][r] = acc[p];
    }
    __syncthreads();
    {
        const int r2 = tid % 96, p2 = tid / 96;   // 4*96 = 384 outputs
        float v = part[p2][0][r2] + part[p2][1][r2] + part[p2][2][r2] + part[p2][3][r2]
                + g_bg[r2];
        bool ii = r2 < NH;
        int n2 = ii ? r2 : r2 - NH;
        float* dst = ii ? g_ig : g_fg;
        dst[(b * NH + n2) * SS + sl0 + p2] = v;
    }
}

// ---------------------------------------------------------------------------
// K_B: mLSTM as linear-attention prefix sum. One block per (b,head),
// 576 threads (thread = position).
// ---------------------------------------------------------------------------
__global__ void kB(const float* __restrict__ on_g,
                   const float* __restrict__ on_b) {
    __shared__ float wsum[18], wmax[18], A_sh;
    __shared__ float wtot[18][20];
    __shared__ float epre[18][20];
    const int bh = blockIdx.x;
    const int b = bh / NH, n = bh % NH;
    const int s = threadIdx.x;               // 576
    const int wid = s >> 5, lane = s & 31;

    float fgv = g_fg[bh * SS + s];
    float igv = g_ig[bh * SS + s];
    float lf = (fgv > 0.f) ? -log1pf(__expf(-fgv)) : (fgv - log1pf(__expf(fgv)));
    float v = lf;
#pragma unroll
    for (int off = 1; off < 32; off <<= 1) {
        float nn = __shfl_up_sync(0xffffffffu, v, off);
        if (lane >= off) v += nn;
    }
    if (lane == 31) wsum[wid] = v;
    __syncthreads();
    float wex = 0.f;
    for (int ww = 0; ww < wid; ww++) wex += wsum[ww];
    const float cums = v + wex;
    const float a = igv - cums;
    float m = a;
#pragma unroll
    for (int off = 1; off < 32; off <<= 1) {
        float nn = __shfl_up_sync(0xffffffffu, m, off);
        if (lane >= off) m = fmaxf(m, nn);
    }
    if (lane == 31) wmax[wid] = m;
    __syncthreads();
    float wexm = -1e30f;
    for (int ww = 0; ww < wid; ww++) wexm = fmaxf(wexm, wmax[ww]);
    const float M = fmaxf(m, wexm);
    if (s == SS - 1) A_sh = M;
    __syncthreads();
    const float A = A_sh;
    const float E = 0.5f * __expf(a - A);     // 0.5 = DH^-0.5 folded in

    float4 q4 = g_q4[bh * SS + s];
    float4 k4 = g_k4[bh * SS + s];
    float4 v4 = g_v4[bh * SS + s];
    float kv[4] = {k4.x, k4.y, k4.z, k4.w};
    float vv[4] = {v4.x, v4.y, v4.z, v4.w};
    float st[20];
#pragma unroll
    for (int j = 0; j < 4; j++) {
        float ek = E * kv[j];
        st[16 + j] = ek;
#pragma unroll
        for (int d = 0; d < 4; d++) st[j * 4 + d] = ek * vv[d];
    }

#pragma unroll
    for (int off = 1; off < 32; off <<= 1) {
        float tmp[20];
#pragma unroll
        for (int c = 0; c < 20; c++) tmp[c] = __shfl_up_sync(0xffffffffu, st[c], off);
        if (lane >= off) {
#pragma unroll
            for (int c = 0; c < 20; c++) st[c] += tmp[c];
        }
    }
    if (lane == 31) {
#pragma unroll
        for (int c = 0; c < 20; c++) wtot[wid][c] = st[c];
    }
    __syncthreads();
    if (wid == 0 && lane < 20) {
        float acc = 0.f;
        for (int ww = 0; ww < 18; ww++) { epre[ww][lane] = acc; acc += wtot[ww][lane]; }
    }
    __syncthreads();
#pragma unroll
    for (int c = 0; c < 20; c++) st[c] += epre[wid][c];

    float qv[4] = {q4.x, q4.y, q4.z, q4.w};
    float o[4] = {0.f, 0.f, 0.f, 0.f};
    float csum = 0.f;
#pragma unroll
    for (int j = 0; j < 4; j++) {
        csum += qv[j] * st[16 + j];
#pragma unroll
        for (int d = 0; d < 4; d++) o[d] += qv[j] * st[j * 4 + d];
    }
    float norm = fmaxf(fabsf(csum), __expf(-(cums + A)));
    float denom = norm + 1e-6f * __expf(M - A);
    float inv = 1.f / denom;
    float h0 = o[0] * inv, h1 = o[1] * inv, h2 = o[2] * inv, h3 = o[3] * inv;

    float mm = (h0 + h1 + h2 + h3) * 0.25f;
    float d0 = h0 - mm, d1 = h1 - mm, d2 = h2 - mm, d3 = h3 - mm;
    float var = (d0 * d0 + d1 * d1 + d2 * d2 + d3 * d3) * 0.25f;
    float r = rsqrtf(var + 1e-5f);
    float4 og = *(const float4*)(on_g + n * 4);
    float4 ob = *(const float4*)(on_b + n * 4);
    float4 out = make_float4(d0 * r * og.x + ob.x,
                             d1 * r * og.y + ob.y,
                             d2 * r * og.z + ob.z,
                             d3 * r * og.w + ob.w);
    *(float4*)(g_hnorm + (b * SS + s) * INNER + n * 4) = out;
}

// ---------------------------------------------------------------------------
// K_C: skip + z-gate + down-proj + residual. 2 positions per block,
// 576 blocks x 384 threads = 96 channels x 4 f-slices of 48.
// ---------------------------------------------------------------------------
__global__ void kC(const float* __restrict__ x,
                   const float* __restrict__ skip,
                   const float* __restrict__ b_down,
                   float* __restrict__ out) {
    __shared__ __align__(16) float hs[2 * INNER];
    __shared__ __align__(16) float part[2][4][100];
    const int g0 = blockIdx.x * 2;
    const int tid = threadIdx.x;            // 384
    {
        int p = tid / INNER, d = tid % INNER;    // 384 = 2*192, one element/thread
        int g = g0 + p;
        float hn = g_hnorm[g * INNER + d];
        float xc = g_xconv[g * INNER + d];
        float z = g_z[g * INNER + d];
        float sg = 1.f / (1.f + __expf(-z));
        hs[tid] = (hn + skip[d] * xc) * (z * sg);
    }
    __syncthreads();

    const int c = tid % 96;
    const int slice = tid / 96;             // 4 slices of 48
    const int f0 = slice * 48;
    float acc0 = 0.f, acc1 = 0.f;
    for (int f = 0; f < 48; f++) {
        float w = g_wdT[(f0 + f) * DIMC + c];
        acc0 += w * hs[f0 + f];
        acc1 += w * hs[INNER + f0 + f];
    }
    part[0][slice][c] = acc0;
    part[1][slice][c] = acc1;
    __syncthreads();

    if (tid < 192) {
        const int b = g0 / SS, s0 = g0 % SS;
        const int c2 = tid % 96, p2 = tid / 96;
        float v = part[p2][0][c2] + part[p2][1][c2] + part[p2][2][c2] + part[p2][3][c2]
                + b_down[c2];
        int gi = (b * DIMC + c2) * SS + s0 + p2;
        out[gi] = x[gi] + v;
    }
}

// ---------------------------------------------------------------------------
extern "C" void kernel_launch(void* const* d_in, const int* in_sizes, int n_in,
                              void* d_out, int out_size) {
    const float* x      = (const float*)d_in[0];
    const float* ln_g   = (const float*)d_in[1];
    const float* ln_b   = (const float*)d_in[2];
    const float* w_up   = (const float*)d_in[3];
    const float* b_up   = (const float*)d_in[4];
    const float* w_q    = (const float*)d_in[5];
    const float* b_q    = (const float*)d_in[6];
    const float* w_k    = (const float*)d_in[7];
    const float* b_k    = (const float*)d_in[8];
    const float* w_v    = (const float*)d_in[9];
    const float* b_v    = (const float*)d_in[10];
    const float* w_conv = (const float*)d_in[11];
    const float* b_conv = (const float*)d_in[12];
    const float* w_ig   = (const float*)d_in[13];
    const float* b_ig   = (const float*)d_in[14];
    const float* w_fg   = (const float*)d_in[15];
    const float* b_fg   = (const float*)d_in[16];
    const float* on_g   = (const float*)d_in[17];
    const float* on_b   = (const float*)d_in[18];
    const float* skip   = (const float*)d_in[19];
    const float* w_down = (const float*)d_in[20];
    const float* b_down = (const float*)d_in[21];
    float* out = (float*)d_out;

    const int ntrans = DIMC * 384 + 384 * 96 + INNER * DIMC + 96;   // 92256
    kT<<<(ntrans + 255) / 256, 256>>>(w_up, w_q, b_q, w_k, b_k, w_v, b_v,
                                      w_ig, b_ig, w_fg, b_fg, w_down);
    kA<<<GTOT / 4, 384>>>(x, ln_g, ln_b, b_up, w_conv, b_conv,
                          w_q, b_q, w_k, b_k, w_v, b_v);
    kB<<<NBH, SS>>>(on_g, on_b);
    kC<<<GTOT / 2, 384>>>(x, skip, b_down, out);
}

// round 9
// speedup vs baseline: 1.4811x; 1.4811x over previous
#include <cuda_runtime.h>
#include <math.h>

#define BB 2
#define DIMC 96
#define INNER 192
#define NH 48
#define SS 576
#define GTOT (BB*SS)   // 1152
#define F3 (3*INNER)   // 576
#define NBH (BB*NH)    // 96
#define NBLK 192
#define NTHR 576
#define PB 6           // positions per block in phases A/C

// Scratch (device globals; no allocation allowed)
__device__ float g_z[GTOT * INNER];
__device__ float g_xconv[GTOT * INNER];
__device__ float4 g_q4[NBH * SS];
__device__ float4 g_k4[NBH * SS];
__device__ float4 g_v4[NBH * SS];
__device__ float g_ig[NBH * SS];
__device__ float g_fg[NBH * SS];
__device__ float g_hnorm[GTOT * INNER];
__device__ float g_wupT[DIMC * 384];   // [c][o]
__device__ float g_wgT[F3 * 96];       // [f][j] j<48: ig, else fg
__device__ float g_wdT[INNER * DIMC];  // [f][c]
__device__ unsigned g_cnt;             // grid-barrier arrival counter

__global__ void kInit() { g_cnt = 0u; }

// Shared pool offsets (floats)
#define H_OFF    0          // 9 x 100
#define MU_OFF   912        // 9
#define IV_OFF   928        // 9
#define XIM_OFF  944        // 9 x 192
#define SQ_OFF   2672       // 6 x 576
#define PART_OFF 6128       // 6 x 6 x 100
#define POOL_SZ  9728       // floats = 38912 B

__global__ void __launch_bounds__(NTHR, 2)
kFused(const float* __restrict__ x,
       const float* __restrict__ ln_g, const float* __restrict__ ln_b,
       const float* __restrict__ w_up, const float* __restrict__ b_up,
       const float* __restrict__ w_q, const float* __restrict__ b_q,
       const float* __restrict__ w_k, const float* __restrict__ b_k,
       const float* __restrict__ w_v, const float* __restrict__ b_v,
       const float* __restrict__ w_conv, const float* __restrict__ b_conv,
       const float* __restrict__ w_ig, const float* __restrict__ b_ig,
       const float* __restrict__ w_fg, const float* __restrict__ b_fg,
       const float* __restrict__ on_g, const float* __restrict__ on_b,
       const float* __restrict__ skip,
       const float* __restrict__ w_down, const float* __restrict__ b_down,
       float* __restrict__ out) {
    __shared__ __align__(16) float pool[POOL_SZ];
    const int tid = threadIdx.x;
    const int wid = tid >> 5, lane = tid & 31;
    const int g0 = blockIdx.x * PB;
    const int b = g0 / SS, sl0 = g0 % SS;    // 96 blocks per batch, no straddle

    // grid barrier: monotonic counter, absolute targets (g_cnt zeroed by kInit)
    auto gridbar = [&](unsigned k) {
        __syncthreads();
        if (tid == 0) {
            __threadfence();
            atomicAdd(&g_cnt, 1u);
            const unsigned tgt = k * (unsigned)NBLK;
            while ((int)(atomicAdd(&g_cnt, 0u) - tgt) < 0) __nanosleep(40);
            __threadfence();
        }
        __syncthreads();
    };

    // ================= Phase T: weight transposes (1 elem / thread) ========
    {
        int idx = blockIdx.x * NTHR + tid;            // 0..110591
        if (idx < DIMC * 384) {
            int c = idx / 384, o = idx % 384;
            g_wupT[c * 384 + o] = w_up[o * DIMC + c];
        } else if (idx < DIMC * 384 + F3 * 96) {
            int i2 = idx - DIMC * 384;
            int f = i2 / 96, j = i2 % 96;
            g_wgT[f * 96 + j] = (j < NH) ? w_ig[j * F3 + f] : w_fg[(j - NH) * F3 + f];
        } else {
            int i2 = idx - DIMC * 384 - F3 * 96;      // < 18432
            int f = i2 / DIMC, c = i2 % DIMC;
            g_wdT[f * DIMC + c] = w_down[c * INNER + f];
        }
    }
    gridbar(1);

    // ================= Phase A: LN + up-proj + conv + qkv + gates ==========
    {
        // load x (9 rows: sloc = sl0-3+hp)
        for (int i = tid; i < 9 * DIMC; i += NTHR) {
            int hp = i / DIMC, c = i % DIMC;
            int sloc = sl0 - 3 + hp;
            pool[H_OFF + hp * 100 + c] = (sloc >= 0) ? x[(b * DIMC + c) * SS + sloc] : 0.f;
        }
        __syncthreads();
        if (wid < 9) {
            float sum = 0.f, sqv = 0.f;
            for (int c = lane; c < DIMC; c += 32) {
                float v = pool[H_OFF + wid * 100 + c];
                sum += v; sqv += v * v;
            }
#pragma unroll
            for (int off = 16; off > 0; off >>= 1) {
                sum += __shfl_down_sync(0xffffffffu, sum, off);
                sqv += __shfl_down_sync(0xffffffffu, sqv, off);
            }
            if (lane == 0) {
                float m = sum * (1.f / DIMC);
                float var = sqv * (1.f / DIMC) - m * m;
                pool[MU_OFF + wid] = m;
                pool[IV_OFF + wid] = rsqrtf(var + 1e-5f);
            }
        }
        __syncthreads();
        for (int i = tid; i < 9 * DIMC; i += NTHR) {
            int hp = i / DIMC, c = i % DIMC;
            pool[H_OFF + hp * 100 + c] =
                (pool[H_OFF + hp * 100 + c] - pool[MU_OFF + hp]) * pool[IV_OFF + hp]
                * ln_g[c] + ln_b[c];
        }
        __syncthreads();

        // up-proj
        if (tid < INNER) {
            const int o = tid;
            float acc[9];
            float bias = b_up[o];
#pragma unroll
            for (int p = 0; p < 9; p++) acc[p] = bias;
            for (int c = 0; c < DIMC; c++) {
                float w = g_wupT[c * 384 + o];
                float* hr = &pool[H_OFF + c];
#pragma unroll
                for (int p = 0; p < 9; p++) acc[p] += w * hr[p * 100];
            }
#pragma unroll
            for (int p = 0; p < 9; p++) pool[XIM_OFF + p * INNER + o] = acc[p];
        } else if (tid < 384) {
            const int o = tid;
            float acc[PB];
            float bias = b_up[o];
#pragma unroll
            for (int p = 0; p < PB; p++) acc[p] = bias;
            for (int c = 0; c < DIMC; c++) {
                float w = g_wupT[c * 384 + o];
                float* hr = &pool[H_OFF + c];
#pragma unroll
                for (int p = 0; p < PB; p++) acc[p] += w * hr[(p + 3) * 100];
            }
#pragma unroll
            for (int p = 0; p < PB; p++)
                g_z[(g0 + p) * INNER + (o - INNER)] = acc[p];
        }
        __syncthreads();

        // conv + SiLU + qkv (PB*48 = 288 active)
        if (tid < PB * NH) {
            const int p = tid / NH, n = tid % NH;
            float xc[4];
#pragma unroll
            for (int d = 0; d < 4; d++) xc[d] = b_conv[n * 4 + d];
#pragma unroll
            for (int k = 0; k < 4; k++) {
                if (sl0 + p - 3 + k >= 0) {
                    const float* xr = &pool[XIM_OFF + (p + k) * INNER + n * 4];
#pragma unroll
                    for (int d = 0; d < 4; d++)
                        xc[d] += w_conv[(n * 4 + d) * 4 + k] * xr[d];
                }
            }
#pragma unroll
            for (int d = 0; d < 4; d++) {
                float sg = 1.f / (1.f + __expf(-xc[d]));
                xc[d] *= sg;
            }
            const float* xmr = &pool[XIM_OFF + (p + 3) * INNER + n * 4];
            float xm0 = xmr[0], xm1 = xmr[1], xm2 = xmr[2], xm3 = xmr[3];

            *(float4*)(g_xconv + (g0 + p) * INNER + n * 4) =
                make_float4(xc[0], xc[1], xc[2], xc[3]);

            float q[4], kk[4], v[4];
#pragma unroll
            for (int o = 0; o < 4; o++) {
                const float* wq = w_q + n * 16 + o * 4;
                q[o] = b_q[n * 4 + o] + wq[0]*xc[0] + wq[1]*xc[1] + wq[2]*xc[2] + wq[3]*xc[3];
                const float* wk = w_k + n * 16 + o * 4;
                kk[o] = b_k[n * 4 + o] + wk[0]*xc[0] + wk[1]*xc[1] + wk[2]*xc[2] + wk[3]*xc[3];
                const float* wv = w_v + n * 16 + o * 4;
                v[o] = b_v[n * 4 + o] + wv[0]*xm0 + wv[1]*xm1 + wv[2]*xm2 + wv[3]*xm3;
            }
            float4 qf = make_float4(q[0], q[1], q[2], q[3]);
            float4 kf = make_float4(kk[0], kk[1], kk[2], kk[3]);
            float4 vf = make_float4(v[0], v[1], v[2], v[3]);
            *(float4*)(&pool[SQ_OFF + p * F3 + n * 4])             = qf;
            *(float4*)(&pool[SQ_OFF + p * F3 + INNER + n * 4])     = kf;
            *(float4*)(&pool[SQ_OFF + p * F3 + 2 * INNER + n * 4]) = vf;
            int hidx = (b * NH + n) * SS + sl0 + p;
            g_q4[hidx] = qf;
            g_k4[hidx] = kf;
            g_v4[hidx] = vf;
        }
        __syncthreads();

        // gates: 96 rows x 6 f-slices of 96
        {
            const int r = tid % 96;
            const int slice = tid / 96;       // 0..5
            const int f0 = slice * 96;
            float acc[PB];
#pragma unroll
            for (int p = 0; p < PB; p++) acc[p] = 0.f;
            for (int f = 0; f < 96; f++) {
                float w = g_wgT[(f0 + f) * 96 + r];
#pragma unroll
                for (int p = 0; p < PB; p++) acc[p] += w * pool[SQ_OFF + p * F3 + f0 + f];
            }
#pragma unroll
            for (int p = 0; p < PB; p++)
                pool[PART_OFF + (p * 6 + slice) * 100 + r] = acc[p];
        }
        __syncthreads();
        {
            const int r2 = tid % 96, p2 = tid / 96;  // 576 outputs
            float v = 0.f;
#pragma unroll
            for (int sl = 0; sl < 6; sl++)
                v += pool[PART_OFF + (p2 * 6 + sl) * 100 + r2];
            bool ii = r2 < NH;
            int n2 = ii ? r2 : r2 - NH;
            v += ii ? b_ig[n2] : b_fg[n2];
            float* dst = ii ? g_ig : g_fg;
            dst[(b * NH + n2) * SS + sl0 + p2] = v;
        }
    }
    gridbar(2);

    // ================= Phase B: mLSTM scan (blocks 0..95) ==================
    if (blockIdx.x < NBH) {
        float* wsum = pool;          // 18
        float* wmax = pool + 32;     // 18
        float* A_sh = pool + 63;     // 1
        float* wtot = pool + 64;     // 18*20
        float* epre = pool + 424;    // 18*20
        const int bh = blockIdx.x;
        const int bb = bh / NH, n = bh % NH;
        const int s = tid;

        float fgv = g_fg[bh * SS + s];
        float igv = g_ig[bh * SS + s];
        float lf = (fgv > 0.f) ? -log1pf(__expf(-fgv)) : (fgv - log1pf(__expf(fgv)));
        float v = lf;
#pragma unroll
        for (int off = 1; off < 32; off <<= 1) {
            float nn = __shfl_up_sync(0xffffffffu, v, off);
            if (lane >= off) v += nn;
        }
        if (lane == 31) wsum[wid] = v;
        __syncthreads();
        float wex = 0.f;
        for (int ww = 0; ww < wid; ww++) wex += wsum[ww];
        const float cums = v + wex;
        const float a = igv - cums;
        float m = a;
#pragma unroll
        for (int off = 1; off < 32; off <<= 1) {
            float nn = __shfl_up_sync(0xffffffffu, m, off);
            if (lane >= off) m = fmaxf(m, nn);
        }
        if (lane == 31) wmax[wid] = m;
        __syncthreads();
        float wexm = -1e30f;
        for (int ww = 0; ww < wid; ww++) wexm = fmaxf(wexm, wmax[ww]);
        const float M = fmaxf(m, wexm);
        if (s == SS - 1) *A_sh = M;
        __syncthreads();
        const float A = *A_sh;
        const float E = 0.5f * __expf(a - A);

        float4 q4 = g_q4[bh * SS + s];
        float4 k4 = g_k4[bh * SS + s];
        float4 v4 = g_v4[bh * SS + s];
        float kv[4] = {k4.x, k4.y, k4.z, k4.w};
        float vv[4] = {v4.x, v4.y, v4.z, v4.w};
        float st[20];
#pragma unroll
        for (int j = 0; j < 4; j++) {
            float ek = E * kv[j];
            st[16 + j] = ek;
#pragma unroll
            for (int d = 0; d < 4; d++) st[j * 4 + d] = ek * vv[d];
        }
#pragma unroll
        for (int off = 1; off < 32; off <<= 1) {
            float tmp[20];
#pragma unroll
            for (int c = 0; c < 20; c++) tmp[c] = __shfl_up_sync(0xffffffffu, st[c], off);
            if (lane >= off) {
#pragma unroll
                for (int c = 0; c < 20; c++) st[c] += tmp[c];
            }
        }
        if (lane == 31) {
#pragma unroll
            for (int c = 0; c < 20; c++) wtot[wid * 20 + c] = st[c];
        }
        __syncthreads();
        if (wid == 0 && lane < 20) {
            float acc = 0.f;
            for (int ww = 0; ww < 18; ww++) { epre[ww * 20 + lane] = acc; acc += wtot[ww * 20 + lane]; }
        }
        __syncthreads();
#pragma unroll
        for (int c = 0; c < 20; c++) st[c] += epre[wid * 20 + c];

        float qv[4] = {q4.x, q4.y, q4.z, q4.w};
        float o[4] = {0.f, 0.f, 0.f, 0.f};
        float csum = 0.f;
#pragma unroll
        for (int j = 0; j < 4; j++) {
            csum += qv[j] * st[16 + j];
#pragma unroll
            for (int d = 0; d < 4; d++) o[d] += qv[j] * st[j * 4 + d];
        }
        float norm = fmaxf(fabsf(csum), __expf(-(cums + A)));
        float denom = norm + 1e-6f * __expf(M - A);
        float inv = 1.f / denom;
        float h0 = o[0] * inv, h1 = o[1] * inv, h2 = o[2] * inv, h3 = o[3] * inv;

        float mm = (h0 + h1 + h2 + h3) * 0.25f;
        float d0 = h0 - mm, d1 = h1 - mm, d2 = h2 - mm, d3 = h3 - mm;
        float var = (d0*d0 + d1*d1 + d2*d2 + d3*d3) * 0.25f;
        float r = rsqrtf(var + 1e-5f);
        float4 og = *(const float4*)(on_g + n * 4);
        float4 ob = *(const float4*)(on_b + n * 4);
        float4 outv = make_float4(d0 * r * og.x + ob.x,
                                  d1 * r * og.y + ob.y,
                                  d2 * r * og.z + ob.z,
                                  d3 * r * og.w + ob.w);
        *(float4*)(g_hnorm + (bb * SS + s) * INNER + n * 4) = outv;
    }
    gridbar(3);

    // ================= Phase C: skip + z-gate + down-proj + residual =======
    {
        for (int i = tid; i < PB * INNER; i += NTHR) {     // 1152
            int p = i / INNER, d = i % INNER;
            int g = g0 + p;
            float hn = g_hnorm[g * INNER + d];
            float xc = g_xconv[g * INNER + d];
            float z = g_z[g * INNER + d];
            float sg = 1.f / (1.f + __expf(-z));
            pool[i] = (hn + skip[d] * xc) * (z * sg);
        }
        __syncthreads();

        const int c = tid % 96;
        const int slice = tid / 96;          // 6 slices of 32
        const int f0 = slice * 32;
        float acc[PB];
#pragma unroll
        for (int p = 0; p < PB; p++) acc[p] = 0.f;
        for (int f = 0; f < 32; f++) {
            float w = g_wdT[(f0 + f) * DIMC + c];
#pragma unroll
            for (int p = 0; p < PB; p++) acc[p] += w * pool[p * INNER + f0 + f];
        }
        __syncthreads();   // pool[0..1151] reads done before partials overwrite? (separate region)
#pragma unroll
        for (int p = 0; p < PB; p++)
            pool[PART_OFF + (p * 6 + slice) * 100 + c] = acc[p];
        __syncthreads();

        {
            const int c2 = tid % 96, p2 = tid / 96;        // 576 outputs
            float v = b_down[c2];
#pragma unroll
            for (int sl = 0; sl < 6; sl++)
                v += pool[PART_OFF + (p2 * 6 + sl) * 100 + c2];
            int gi = (b * DIMC + c2) * SS + sl0 + p2;
            out[gi] = x[gi] + v;
        }
    }
}

// ---------------------------------------------------------------------------
extern "C" void kernel_launch(void* const* d_in, const int* in_sizes, int n_in,
                              void* d_out, int out_size) {
    const float* x      = (const float*)d_in[0];
    const float* ln_g   = (const float*)d_in[1];
    const float* ln_b   = (const float*)d_in[2];
    const float* w_up   = (const float*)d_in[3];
    const float* b_up   = (const float*)d_in[4];
    const float* w_q    = (const float*)d_in[5];
    const float* b_q    = (const float*)d_in[6];
    const float* w_k    = (const float*)d_in[7];
    const float* b_k    = (const float*)d_in[8];
    const float* w_v    = (const float*)d_in[9];
    const float* b_v    = (const float*)d_in[10];
    const float* w_conv = (const float*)d_in[11];
    const float* b_conv = (const float*)d_in[12];
    const float* w_ig   = (const float*)d_in[13];
    const float* b_ig   = (const float*)d_in[14];
    const float* w_fg   = (const float*)d_in[15];
    const float* b_fg   = (const float*)d_in[16];
    const float* on_g   = (const float*)d_in[17];
    const float* on_b   = (const float*)d_in[18];
    const float* skip   = (const float*)d_in[19];
    const float* w_down = (const float*)d_in[20];
    const float* b_down = (const float*)d_in[21];
    float* out = (float*)d_out;

    kInit<<<1, 1>>>();
    kFused<<<NBLK, NTHR>>>(x, ln_g, ln_b, w_up, b_up, w_q, b_q, w_k, b_k,
                           w_v, b_v, w_conv, b_conv, w_ig, b_ig, w_fg, b_fg,
                           on_g, on_b, skip, w_down, b_down, out);
}

// round 10
// speedup vs baseline: 1.5403x; 1.0400x over previous
#include <cuda_runtime.h>
#include <math.h>

#define BB 2
#define DIMC 96
#define INNER 192
#define NH 48
#define SS 576
#define GTOT (BB*SS)   // 1152
#define F3 (3*INNER)   // 576
#define NBH (BB*NH)    // 96

// Scratch (device globals; no allocation allowed)
__device__ float g_z[GTOT * INNER];
__device__ float g_xconv[GTOT * INNER];
__device__ float4 g_q4[NBH * SS];
__device__ float4 g_k4[NBH * SS];
__device__ float4 g_v4[NBH * SS];
__device__ float g_ig[NBH * SS];
__device__ float g_fg[NBH * SS];
__device__ float g_hnorm[GTOT * INNER];
__device__ float g_wupT[DIMC * 384];   // [c][o]
__device__ float g_wgT[F3 * 96];       // [f][j] j<48: ig, else fg
__device__ float g_wdT[INNER * DIMC];  // [f][c]

// ---------------------------------------------------------------------------
// kT: weight transposes
// ---------------------------------------------------------------------------
__global__ void kT(const float* __restrict__ w_up,
                   const float* __restrict__ w_ig,
                   const float* __restrict__ w_fg,
                   const float* __restrict__ w_down) {
    int i = blockIdx.x * 256 + threadIdx.x;
    if (i < DIMC * 384) {
        int c = i / 384, o = i % 384;
        g_wupT[c * 384 + o] = w_up[o * DIMC + c];
        return;
    }
    i -= DIMC * 384;
    if (i < F3 * 96) {
        int f = i / 96, j = i % 96;
        g_wgT[f * 96 + j] = (j < NH) ? w_ig[j * F3 + f] : w_fg[(j - NH) * F3 + f];
        return;
    }
    i -= F3 * 96;
    if (i < INNER * DIMC) {
        int f = i / DIMC, c = i % DIMC;
        g_wdT[f * DIMC + c] = w_down[c * INNER + f];
    }
}

// ---------------------------------------------------------------------------
// K_A: LN + up-proj (8 main + 3 halo rows) + causal conv + SiLU + qkv +
// gate pre-activations. 144 blocks x 384 threads.
// ---------------------------------------------------------------------------
__global__ void kA(const float* __restrict__ x,
                   const float* __restrict__ ln_g,
                   const float* __restrict__ ln_b,
                   const float* __restrict__ b_up,
                   const float* __restrict__ w_conv,
                   const float* __restrict__ b_conv,
                   const float* __restrict__ w_q, const float* __restrict__ b_q,
                   const float* __restrict__ w_k, const float* __restrict__ b_k,
                   const float* __restrict__ w_v, const float* __restrict__ b_v,
                   const float* __restrict__ b_ig, const float* __restrict__ b_fg) {
    __shared__ __align__(16) float h[11][100];       // LN'd input
    __shared__ float mu[11], iv[11];
    __shared__ __align__(16) float xim[11][INNER];   // x_mlstm half
    __shared__ __align__(16) float sq[8 * F3];       // q|k|v per main position
    __shared__ __align__(16) float part[8][4][100];  // gate split-K partials
    const int g0 = blockIdx.x * 8;
    const int b = g0 / SS, sl0 = g0 % SS;   // 576%8==0: no batch straddle
    const int tid = threadIdx.x;            // 384
    const int wid = tid >> 5, lane = tid & 31;

    for (int i = tid; i < 11 * DIMC; i += 384) {
        int hp = i / DIMC, c = i % DIMC;
        int sloc = sl0 - 3 + hp;
        h[hp][c] = (sloc >= 0) ? x[(b * DIMC + c) * SS + sloc] : 0.f;
    }
    __syncthreads();
    if (wid < 11) {
        float sum = 0.f, sqv = 0.f;
        for (int c = lane; c < DIMC; c += 32) { float v = h[wid][c]; sum += v; sqv += v * v; }
#pragma unroll
        for (int off = 16; off > 0; off >>= 1) {
            sum += __shfl_down_sync(0xffffffffu, sum, off);
            sqv += __shfl_down_sync(0xffffffffu, sqv, off);
        }
        if (lane == 0) {
            float m = sum * (1.f / DIMC);
            float var = sqv * (1.f / DIMC) - m * m;
            mu[wid] = m;
            iv[wid] = rsqrtf(var + 1e-5f);
        }
    }
    __syncthreads();
    for (int i = tid; i < 11 * DIMC; i += 384) {
        int hp = i / DIMC, c = i % DIMC;
        h[hp][c] = (h[hp][c] - mu[hp]) * iv[hp] * ln_g[c] + ln_b[c];
    }
    __syncthreads();

    // up-proj
    if (tid < INNER) {
        const int o = tid;
        float acc[11];
        float bias = b_up[o];
#pragma unroll
        for (int p = 0; p < 11; p++) acc[p] = bias;
        for (int c = 0; c < DIMC; c++) {
            float w = g_wupT[c * 384 + o];
#pragma unroll
            for (int p = 0; p < 11; p++) acc[p] += w * h[p][c];
        }
#pragma unroll
        for (int p = 0; p < 11; p++) xim[p][o] = acc[p];
    } else {
        const int o = tid;                   // z channels
        float acc[8];
        float bias = b_up[o];
#pragma unroll
        for (int p = 0; p < 8; p++) acc[p] = bias;
        for (int c = 0; c < DIMC; c++) {
            float w = g_wupT[c * 384 + o];
#pragma unroll
            for (int p = 0; p < 8; p++) acc[p] += w * h[p + 3][c];
        }
#pragma unroll
        for (int p = 0; p < 8; p++)
            g_z[(g0 + p) * INNER + (o - INNER)] = acc[p];
    }
    __syncthreads();

    // conv + SiLU + qkv: thread = (p, n), 8*48 = 384
    {
        const int p = tid / NH, n = tid % NH;
        float xc[4];
#pragma unroll
        for (int d = 0; d < 4; d++) xc[d] = b_conv[n * 4 + d];
#pragma unroll
        for (int k = 0; k < 4; k++) {
            if (sl0 + p - 3 + k >= 0) {
                const float* xr = &xim[p + k][n * 4];
#pragma unroll
                for (int d = 0; d < 4; d++)
                    xc[d] += w_conv[(n * 4 + d) * 4 + k] * xr[d];
            }
        }
#pragma unroll
        for (int d = 0; d < 4; d++) {
            float sg = 1.f / (1.f + __expf(-xc[d]));
            xc[d] *= sg;
        }
        float xm0 = xim[p + 3][n * 4], xm1 = xim[p + 3][n * 4 + 1];
        float xm2 = xim[p + 3][n * 4 + 2], xm3 = xim[p + 3][n * 4 + 3];

        *(float4*)(g_xconv + (g0 + p) * INNER + n * 4) =
            make_float4(xc[0], xc[1], xc[2], xc[3]);

        float q[4], kk[4], v[4];
#pragma unroll
        for (int o = 0; o < 4; o++) {
            const float* wq = w_q + n * 16 + o * 4;
            q[o] = b_q[n * 4 + o] + wq[0]*xc[0] + wq[1]*xc[1] + wq[2]*xc[2] + wq[3]*xc[3];
            const float* wk = w_k + n * 16 + o * 4;
            kk[o] = b_k[n * 4 + o] + wk[0]*xc[0] + wk[1]*xc[1] + wk[2]*xc[2] + wk[3]*xc[3];
            const float* wv = w_v + n * 16 + o * 4;
            v[o] = b_v[n * 4 + o] + wv[0]*xm0 + wv[1]*xm1 + wv[2]*xm2 + wv[3]*xm3;
        }
        float4 qf = make_float4(q[0], q[1], q[2], q[3]);
        float4 kf = make_float4(kk[0], kk[1], kk[2], kk[3]);
        float4 vf = make_float4(v[0], v[1], v[2], v[3]);
        *(float4*)(sq + p * F3 + n * 4)             = qf;
        *(float4*)(sq + p * F3 + INNER + n * 4)     = kf;
        *(float4*)(sq + p * F3 + 2 * INNER + n * 4) = vf;
        int hidx = (b * NH + n) * SS + sl0 + p;
        g_q4[hidx] = qf;
        g_k4[hidx] = kf;
        g_v4[hidx] = vf;
    }
    __syncthreads();

    // gates: 96 rows x 4 f-slices of 144
    {
        const int r = tid % 96;
        const int slice = tid / 96;
        const int f0 = slice * 144;
        float acc[8];
#pragma unroll
        for (int p = 0; p < 8; p++) acc[p] = 0.f;
        for (int f = 0; f < 144; f++) {
            float w = g_wgT[(f0 + f) * 96 + r];
#pragma unroll
            for (int p = 0; p < 8; p++) acc[p] += w * sq[p * F3 + f0 + f];
        }
#pragma unroll
        for (int p = 0; p < 8; p++) part[p][slice][r] = acc[p];
    }
    __syncthreads();
#pragma unroll
    for (int j = 0; j < 2; j++) {
        int idx = tid + j * 384;             // 0..767
        int r2 = idx % 96, p2 = idx / 96;
        float v = part[p2][0][r2] + part[p2][1][r2] + part[p2][2][r2] + part[p2][3][r2];
        bool ii = r2 < NH;
        int n2 = ii ? r2 : r2 - NH;
        v += ii ? b_ig[n2] : b_fg[n2];
        float* dst = ii ? g_ig : g_fg;
        dst[(b * NH + n2) * SS + sl0 + p2] = v;
    }
}

// ---------------------------------------------------------------------------
// K_B: mLSTM as linear-attention prefix sum (unchanged from R7).
// ---------------------------------------------------------------------------
__global__ void kB(const float* __restrict__ on_g,
                   const float* __restrict__ on_b) {
    __shared__ float wsum[18], wmax[18], A_sh;
    __shared__ float wtot[18][20];
    __shared__ float epre[18][20];
    const int bh = blockIdx.x;
    const int b = bh / NH, n = bh % NH;
    const int s = threadIdx.x;               // 576
    const int wid = s >> 5, lane = s & 31;

    float fgv = g_fg[bh * SS + s];
    float igv = g_ig[bh * SS + s];
    float lf = (fgv > 0.f) ? -log1pf(__expf(-fgv)) : (fgv - log1pf(__expf(fgv)));
    float v = lf;
#pragma unroll
    for (int off = 1; off < 32; off <<= 1) {
        float nn = __shfl_up_sync(0xffffffffu, v, off);
        if (lane >= off) v += nn;
    }
    if (lane == 31) wsum[wid] = v;
    __syncthreads();
    float wex = 0.f;
    for (int ww = 0; ww < wid; ww++) wex += wsum[ww];
    const float cums = v + wex;
    const float a = igv - cums;
    float m = a;
#pragma unroll
    for (int off = 1; off < 32; off <<= 1) {
        float nn = __shfl_up_sync(0xffffffffu, m, off);
        if (lane >= off) m = fmaxf(m, nn);
    }
    if (lane == 31) wmax[wid] = m;
    __syncthreads();
    float wexm = -1e30f;
    for (int ww = 0; ww < wid; ww++) wexm = fmaxf(wexm, wmax[ww]);
    const float M = fmaxf(m, wexm);
    if (s == SS - 1) A_sh = M;
    __syncthreads();
    const float A = A_sh;
    const float E = 0.5f * __expf(a - A);

    float4 q4 = g_q4[bh * SS + s];
    float4 k4 = g_k4[bh * SS + s];
    float4 v4 = g_v4[bh * SS + s];
    float kv[4] = {k4.x, k4.y, k4.z, k4.w};
    float vv[4] = {v4.x, v4.y, v4.z, v4.w};
    float st[20];
#pragma unroll
    for (int j = 0; j < 4; j++) {
        float ek = E * kv[j];
        st[16 + j] = ek;
#pragma unroll
        for (int d = 0; d < 4; d++) st[j * 4 + d] = ek * vv[d];
    }
#pragma unroll
    for (int off = 1; off < 32; off <<= 1) {
        float tmp[20];
#pragma unroll
        for (int c = 0; c < 20; c++) tmp[c] = __shfl_up_sync(0xffffffffu, st[c], off);
        if (lane >= off) {
#pragma unroll
            for (int c = 0; c < 20; c++) st[c] += tmp[c];
        }
    }
    if (lane == 31) {
#pragma unroll
        for (int c = 0; c < 20; c++) wtot[wid][c] = st[c];
    }
    __syncthreads();
    if (wid == 0 && lane < 20) {
        float acc = 0.f;
        for (int ww = 0; ww < 18; ww++) { epre[ww][lane] = acc; acc += wtot[ww][lane]; }
    }
    __syncthreads();
#pragma unroll
    for (int c = 0; c < 20; c++) st[c] += epre[wid][c];

    float qv[4] = {q4.x, q4.y, q4.z, q4.w};
    float o[4] = {0.f, 0.f, 0.f, 0.f};
    float csum = 0.f;
#pragma unroll
    for (int j = 0; j < 4; j++) {
        csum += qv[j] * st[16 + j];
#pragma unroll
        for (int d = 0; d < 4; d++) o[d] += qv[j] * st[j * 4 + d];
    }
    float norm = fmaxf(fabsf(csum), __expf(-(cums + A)));
    float denom = norm + 1e-6f * __expf(M - A);
    float inv = 1.f / denom;
    float h0 = o[0] * inv, h1 = o[1] * inv, h2 = o[2] * inv, h3 = o[3] * inv;

    float mm = (h0 + h1 + h2 + h3) * 0.25f;
    float d0 = h0 - mm, d1 = h1 - mm, d2 = h2 - mm, d3 = h3 - mm;
    float var = (d0*d0 + d1*d1 + d2*d2 + d3*d3) * 0.25f;
    float r = rsqrtf(var + 1e-5f);
    float4 og = *(const float4*)(on_g + n * 4);
    float4 ob = *(const float4*)(on_b + n * 4);
    float4 out = make_float4(d0 * r * og.x + ob.x,
                             d1 * r * og.y + ob.y,
                             d2 * r * og.z + ob.z,
                             d3 * r * og.w + ob.w);
    *(float4*)(g_hnorm + (b * SS + s) * INNER + n * 4) = out;
}

// ---------------------------------------------------------------------------
// K_C: skip + z-gate + down-proj + residual. 8 positions per block,
// 144 blocks x 384 threads. Output staged in smem, written as c-rows of
// 8 consecutive s via float2 (coalesced sectors).
// ---------------------------------------------------------------------------
__global__ void kC(const float* __restrict__ x,
                   const float* __restrict__ skip,
                   const float* __restrict__ b_down,
                   float* __restrict__ out) {
    __shared__ __align__(16) float hs[8 * INNER];    // 6KB; reused as otile
    __shared__ __align__(16) float part[8][4][100];  // 12.8KB
    const int g0 = blockIdx.x * 8;
    const int tid = threadIdx.x;             // 384
    for (int i = tid; i < 8 * INNER; i += 384) {
        int p = i / INNER, d = i % INNER;
        int g = g0 + p;
        float hn = g_hnorm[g * INNER + d];
        float xc = g_xconv[g * INNER + d];
        float z = g_z[g * INNER + d];
        float sg = 1.f / (1.f + __expf(-z));
        hs[i] = (hn + skip[d] * xc) * (z * sg);
    }
    __syncthreads();

    const int c = tid % 96;
    const int slice = tid / 96;              // 4 slices of 48
    const int f0 = slice * 48;
    float acc[8];
#pragma unroll
    for (int p = 0; p < 8; p++) acc[p] = 0.f;
#pragma unroll 4
    for (int f = 0; f < 48; f++) {
        float w = g_wdT[(f0 + f) * DIMC + c];
#pragma unroll
        for (int p = 0; p < 8; p++) acc[p] += w * hs[p * INNER + f0 + f];
    }
    __syncthreads();   // hs reads done (about to reuse hs region as otile)
#pragma unroll
    for (int p = 0; p < 8; p++) part[p][slice][c] = acc[p];
    __syncthreads();

    // reduce + stage into otile[c][p]  (otile = hs region, 96x8)
    float* otile = hs;
#pragma unroll
    for (int j = 0; j < 2; j++) {
        int idx = tid + j * 384;             // 0..767
        int c2 = idx % 96, p2 = idx / 96;
        float v = part[p2][0][c2] + part[p2][1][c2] + part[p2][2][c2] + part[p2][3][c2]
                + b_down[c2];
        otile[c2 * 8 + p2] = v;
    }
    __syncthreads();

    // coalesced write: thread -> one float2 (c, 2 consecutive s)
    {
        const int b = g0 / SS, sl0 = g0 % SS;
        int idx2 = tid * 2;                  // 0..766
        int c2 = idx2 >> 3, po = idx2 & 7;
        int gi = (b * DIMC + c2) * SS + sl0 + po;
        float2 xv = *(const float2*)(x + gi);
        float2 ov = make_float2(xv.x + otile[c2 * 8 + po],
                                xv.y + otile[c2 * 8 + po + 1]);
        *(float2*)(out + gi) = ov;
    }
}

// ---------------------------------------------------------------------------
extern "C" void kernel_launch(void* const* d_in, const int* in_sizes, int n_in,
                              void* d_out, int out_size) {
    const float* x      = (const float*)d_in[0];
    const float* ln_g   = (const float*)d_in[1];
    const float* ln_b   = (const float*)d_in[2];
    const float* w_up   = (const float*)d_in[3];
    const float* b_up   = (const float*)d_in[4];
    const float* w_q    = (const float*)d_in[5];
    const float* b_q    = (const float*)d_in[6];
    const float* w_k    = (const float*)d_in[7];
    const float* b_k    = (const float*)d_in[8];
    const float* w_v    = (const float*)d_in[9];
    const float* b_v    = (const float*)d_in[10];
    const float* w_conv = (const float*)d_in[11];
    const float* b_conv = (const float*)d_in[12];
    const float* w_ig   = (const float*)d_in[13];
    const float* b_ig   = (const float*)d_in[14];
    const float* w_fg   = (const float*)d_in[15];
    const float* b_fg   = (const float*)d_in[16];
    const float* on_g   = (const float*)d_in[17];
    const float* on_b   = (const float*)d_in[18];
    const float* skip   = (const float*)d_in[19];
    const float* w_down = (const float*)d_in[20];
    const float* b_down = (const float*)d_in[21];
    float* out = (float*)d_out;

    const int ntrans = DIMC * 384 + F3 * 96 + INNER * DIMC;   // 110592
    kT<<<(ntrans + 255) / 256, 256>>>(w_up, w_ig, w_fg, w_down);
    kA<<<GTOT / 8, 384>>>(x, ln_g, ln_b, b_up, w_conv, b_conv,
                          w_q, b_q, w_k, b_k, w_v, b_v, b_ig, b_fg);
    kB<<<NBH, SS>>>(on_g, on_b);
    kC<<<GTOT / 8, 384>>>(x, skip, b_down, out);
}

// round 11
// speedup vs baseline: 2.0016x; 1.2995x over previous
#include <cuda_runtime.h>
#include <math.h>

#define BB 2
#define DIMC 96
#define INNER 192
#define NH 48
#define SS 576
#define GTOT (BB*SS)   // 1152
#define F3 (3*INNER)   // 576
#define NBH (BB*NH)    // 96

// Scratch (device globals; no allocation allowed)
__device__ float g_z[GTOT * INNER];
__device__ float g_xconv[GTOT * INNER];
__device__ float4 g_q4[NBH * SS];
__device__ float4 g_k4[NBH * SS];
__device__ float4 g_v4[NBH * SS];
__device__ float g_ig[NBH * SS];
__device__ float g_fg[NBH * SS];
__device__ float g_hstate[GTOT * INNER];   // (hnorm + skip*xconv)*silu(z)
__device__ float g_wupT[DIMC * 384];   // [c][o]
__device__ float g_wgT[F3 * 96];       // [f][j] j<48: ig, else fg
__device__ float g_wdT[INNER * DIMC];  // [f][c]

// ---------------------------------------------------------------------------
// kT: weight transposes (unchanged from R7)
// ---------------------------------------------------------------------------
__global__ void kT(const float* __restrict__ w_up,
                   const float* __restrict__ w_ig,
                   const float* __restrict__ w_fg,
                   const float* __restrict__ w_down) {
    int i = blockIdx.x * 256 + threadIdx.x;
    if (i < DIMC * 384) {
        int c = i / 384, o = i % 384;
        g_wupT[c * 384 + o] = w_up[o * DIMC + c];
        return;
    }
    i -= DIMC * 384;
    if (i < F3 * 96) {
        int f = i / 96, j = i % 96;
        g_wgT[f * 96 + j] = (j < NH) ? w_ig[j * F3 + f] : w_fg[(j - NH) * F3 + f];
        return;
    }
    i -= F3 * 96;
    if (i < INNER * DIMC) {
        int f = i / DIMC, c = i % DIMC;
        g_wdT[f * DIMC + c] = w_down[c * INNER + f];
    }
}

// ---------------------------------------------------------------------------
// K_A: LN + up-proj (4 main + 3 halo) + causal conv + SiLU + qkv + gates.
// 288 blocks x 384 threads (R7 geometry; gates loop re-paired ig/fg).
// ---------------------------------------------------------------------------
__global__ void kA(const float* __restrict__ x,
                   const float* __restrict__ ln_g,
                   const float* __restrict__ ln_b,
                   const float* __restrict__ b_up,
                   const float* __restrict__ w_conv,
                   const float* __restrict__ b_conv,
                   const float* __restrict__ w_q, const float* __restrict__ b_q,
                   const float* __restrict__ w_k, const float* __restrict__ b_k,
                   const float* __restrict__ w_v, const float* __restrict__ b_v,
                   const float* __restrict__ b_ig, const float* __restrict__ b_fg) {
    __shared__ __align__(16) float h[7][100];       // LN'd input (7 rows)
    __shared__ float mu[7], iv[7];
    __shared__ __align__(16) float xim[7][INNER];   // x_mlstm half
    __shared__ __align__(16) float sq[4 * F3];      // q|k|v per main position
    __shared__ __align__(16) float part_i[4][8][48];
    __shared__ __align__(16) float part_f[4][8][48];
    const int g0 = blockIdx.x * 4;
    const int b = g0 / SS, sl0 = g0 % SS;   // blocks never straddle batches
    const int tid = threadIdx.x;            // 384
    const int wid = tid >> 5, lane = tid & 31;

    // ---- load x (7 rows: sloc = sl0-3+hp), zero-invalid
    for (int i = tid; i < 7 * DIMC; i += 384) {
        int hp = i / DIMC, c = i % DIMC;
        int sloc = sl0 - 3 + hp;
        h[hp][c] = (sloc >= 0) ? x[(b * DIMC + c) * SS + sloc] : 0.f;
    }
    __syncthreads();
    // ---- LN stats, warp per row
    if (wid < 7) {
        float sum = 0.f, sqv = 0.f;
        for (int c = lane; c < DIMC; c += 32) { float v = h[wid][c]; sum += v; sqv += v * v; }
#pragma unroll
        for (int off = 16; off > 0; off >>= 1) {
            sum += __shfl_down_sync(0xffffffffu, sum, off);
            sqv += __shfl_down_sync(0xffffffffu, sqv, off);
        }
        if (lane == 0) {
            float m = sum * (1.f / DIMC);
            float var = sqv * (1.f / DIMC) - m * m;
            mu[wid] = m;
            iv[wid] = rsqrtf(var + 1e-5f);
        }
    }
    __syncthreads();
    for (int i = tid; i < 7 * DIMC; i += 384) {
        int hp = i / DIMC, c = i % DIMC;
        h[hp][c] = (h[hp][c] - mu[hp]) * iv[hp] * ln_g[c] + ln_b[c];
    }
    __syncthreads();

    // ---- up-proj (coalesced transposed weights)
    if (tid < INNER) {
        const int o = tid;
        float acc[7];
        float bias = b_up[o];
#pragma unroll
        for (int p = 0; p < 7; p++) acc[p] = bias;
        for (int c = 0; c < DIMC; c++) {
            float w = g_wupT[c * 384 + o];
#pragma unroll
            for (int p = 0; p < 7; p++) acc[p] += w * h[p][c];
        }
#pragma unroll
        for (int p = 0; p < 7; p++) xim[p][o] = acc[p];
    } else {
        const int o = tid;                   // 192..383 -> z channels
        float acc[4];
        float bias = b_up[o];
#pragma unroll
        for (int p = 0; p < 4; p++) acc[p] = bias;
        for (int c = 0; c < DIMC; c++) {
            float w = g_wupT[c * 384 + o];
#pragma unroll
            for (int p = 0; p < 4; p++) acc[p] += w * h[p + 3][c];
        }
#pragma unroll
        for (int p = 0; p < 4; p++)
            g_z[(g0 + p) * INNER + (o - INNER)] = acc[p];
    }
    __syncthreads();

    // ---- conv + SiLU + qkv: thread = (p, n), 4*48 = 192 active
    if (tid < 192) {
        const int p = tid / NH, n = tid % NH;
        float xc[4];
#pragma unroll
        for (int d = 0; d < 4; d++) xc[d] = b_conv[n * 4 + d];
#pragma unroll
        for (int k = 0; k < 4; k++) {
            if (sl0 + p - 3 + k >= 0) {
                const float* xr = &xim[p + k][n * 4];
#pragma unroll
                for (int d = 0; d < 4; d++)
                    xc[d] += w_conv[(n * 4 + d) * 4 + k] * xr[d];
            }
        }
#pragma unroll
        for (int d = 0; d < 4; d++) {
            float sg = 1.f / (1.f + __expf(-xc[d]));
            xc[d] *= sg;
        }
        float xm0 = xim[p + 3][n * 4], xm1 = xim[p + 3][n * 4 + 1];
        float xm2 = xim[p + 3][n * 4 + 2], xm3 = xim[p + 3][n * 4 + 3];

        *(float4*)(g_xconv + (g0 + p) * INNER + n * 4) =
            make_float4(xc[0], xc[1], xc[2], xc[3]);

        float q[4], kk[4], v[4];
#pragma unroll
        for (int o = 0; o < 4; o++) {
            const float* wq = w_q + n * 16 + o * 4;
            q[o] = b_q[n * 4 + o] + wq[0]*xc[0] + wq[1]*xc[1] + wq[2]*xc[2] + wq[3]*xc[3];
            const float* wk = w_k + n * 16 + o * 4;
            kk[o] = b_k[n * 4 + o] + wk[0]*xc[0] + wk[1]*xc[1] + wk[2]*xc[2] + wk[3]*xc[3];
            const float* wv = w_v + n * 16 + o * 4;
            v[o] = b_v[n * 4 + o] + wv[0]*xm0 + wv[1]*xm1 + wv[2]*xm2 + wv[3]*xm3;
        }
        float4 qf = make_float4(q[0], q[1], q[2], q[3]);
        float4 kf = make_float4(kk[0], kk[1], kk[2], kk[3]);
        float4 vf = make_float4(v[0], v[1], v[2], v[3]);
        *(float4*)(sq + p * F3 + n * 4)             = qf;
        *(float4*)(sq + p * F3 + INNER + n * 4)     = kf;
        *(float4*)(sq + p * F3 + 2 * INNER + n * 4) = vf;
        int hidx = (b * NH + n) * SS + sl0 + p;
        g_q4[hidx] = qf;
        g_k4[hidx] = kf;
        g_v4[hidx] = vf;
    }
    __syncthreads();

    // ---- gates, ig/fg paired: thread = (head j, slice of 72 f)
    {
        const int jn = tid % 48;
        const int slice = tid / 48;          // 0..7
        const int f0 = slice * 72;
        float ai[4], af[4];
#pragma unroll
        for (int p = 0; p < 4; p++) { ai[p] = 0.f; af[p] = 0.f; }
        for (int f = 0; f < 72; f++) {
            const float* wrow = &g_wgT[(f0 + f) * 96];
            float wi = wrow[jn];
            float wf = wrow[48 + jn];
#pragma unroll
            for (int p = 0; p < 4; p++) {
                float s = sq[p * F3 + f0 + f];
                ai[p] += wi * s;
                af[p] += wf * s;
            }
        }
#pragma unroll
        for (int p = 0; p < 4; p++) { part_i[p][slice][jn] = ai[p]; part_f[p][slice][jn] = af[p]; }
    }
    __syncthreads();
    {
        const int r2 = tid % 96, p2 = tid / 96;   // 384 outputs
        bool ii = r2 < NH;
        int n2 = ii ? r2 : r2 - NH;
        float v = 0.f;
#pragma unroll
        for (int sl = 0; sl < 8; sl++)
            v += ii ? part_i[p2][sl][n2] : part_f[p2][sl][n2];
        v += ii ? b_ig[n2] : b_fg[n2];
        float* dst = ii ? g_ig : g_fg;
        dst[(b * NH + n2) * SS + sl0 + p2] = v;
    }
}

// ---------------------------------------------------------------------------
// K_B: mLSTM linear-attention prefix sum + MH-norm + fused skip/z epilogue.
// One block per (b,head), 576 threads.
// ---------------------------------------------------------------------------
__global__ void kB(const float* __restrict__ on_g,
                   const float* __restrict__ on_b,
                   const float* __restrict__ skip) {
    __shared__ float wsum[18], wmax[18], A_sh;
    __shared__ float wtot[18][20];
    __shared__ float epre[18][20];
    const int bh = blockIdx.x;
    const int b = bh / NH, n = bh % NH;
    const int s = threadIdx.x;               // 576
    const int wid = s >> 5, lane = s & 31;

    float fgv = g_fg[bh * SS + s];
    float igv = g_ig[bh * SS + s];
    float lf = (fgv > 0.f) ? -log1pf(__expf(-fgv)) : (fgv - log1pf(__expf(fgv)));
    float v = lf;
#pragma unroll
    for (int off = 1; off < 32; off <<= 1) {
        float nn = __shfl_up_sync(0xffffffffu, v, off);
        if (lane >= off) v += nn;
    }
    if (lane == 31) wsum[wid] = v;
    __syncthreads();
    float wex = 0.f;
    for (int ww = 0; ww < wid; ww++) wex += wsum[ww];
    const float cums = v + wex;
    const float a = igv - cums;
    float m = a;
#pragma unroll
    for (int off = 1; off < 32; off <<= 1) {
        float nn = __shfl_up_sync(0xffffffffu, m, off);
        if (lane >= off) m = fmaxf(m, nn);
    }
    if (lane == 31) wmax[wid] = m;
    __syncthreads();
    float wexm = -1e30f;
    for (int ww = 0; ww < wid; ww++) wexm = fmaxf(wexm, wmax[ww]);
    const float M = fmaxf(m, wexm);
    if (s == SS - 1) A_sh = M;
    __syncthreads();
    const float A = A_sh;
    const float E = 0.5f * __expf(a - A);

    float4 q4 = g_q4[bh * SS + s];
    float4 k4 = g_k4[bh * SS + s];
    float4 v4 = g_v4[bh * SS + s];
    float kv[4] = {k4.x, k4.y, k4.z, k4.w};
    float vv[4] = {v4.x, v4.y, v4.z, v4.w};
    float st[20];
#pragma unroll
    for (int j = 0; j < 4; j++) {
        float ek = E * kv[j];
        st[16 + j] = ek;
#pragma unroll
        for (int d = 0; d < 4; d++) st[j * 4 + d] = ek * vv[d];
    }
#pragma unroll
    for (int off = 1; off < 32; off <<= 1) {
        float tmp[20];
#pragma unroll
        for (int c = 0; c < 20; c++) tmp[c] = __shfl_up_sync(0xffffffffu, st[c], off);
        if (lane >= off) {
#pragma unroll
            for (int c = 0; c < 20; c++) st[c] += tmp[c];
        }
    }
    if (lane == 31) {
#pragma unroll
        for (int c = 0; c < 20; c++) wtot[wid][c] = st[c];
    }
    __syncthreads();
    if (wid == 0 && lane < 20) {
        float acc = 0.f;
        for (int ww = 0; ww < 18; ww++) { epre[ww][lane] = acc; acc += wtot[ww][lane]; }
    }
    __syncthreads();
#pragma unroll
    for (int c = 0; c < 20; c++) st[c] += epre[wid][c];

    float qv[4] = {q4.x, q4.y, q4.z, q4.w};
    float o[4] = {0.f, 0.f, 0.f, 0.f};
    float csum = 0.f;
#pragma unroll
    for (int j = 0; j < 4; j++) {
        csum += qv[j] * st[16 + j];
#pragma unroll
        for (int d = 0; d < 4; d++) o[d] += qv[j] * st[j * 4 + d];
    }
    float norm = fmaxf(fabsf(csum), __expf(-(cums + A)));
    float denom = norm + 1e-6f * __expf(M - A);
    float inv = 1.f / denom;
    float h0 = o[0] * inv, h1 = o[1] * inv, h2 = o[2] * inv, h3 = o[3] * inv;

    float mm = (h0 + h1 + h2 + h3) * 0.25f;
    float d0 = h0 - mm, d1 = h1 - mm, d2 = h2 - mm, d3 = h3 - mm;
    float var = (d0*d0 + d1*d1 + d2*d2 + d3*d3) * 0.25f;
    float r = rsqrtf(var + 1e-5f);
    float4 og = *(const float4*)(on_g + n * 4);
    float4 ob = *(const float4*)(on_b + n * 4);
    float hn0 = d0 * r * og.x + ob.x;
    float hn1 = d1 * r * og.y + ob.y;
    float hn2 = d2 * r * og.z + ob.z;
    float hn3 = d3 * r * og.w + ob.w;

    // fused epilogue: hstate = (hnorm + skip*xconv) * silu(z)
    const int g = b * SS + s;
    float4 xc4 = *(const float4*)(g_xconv + g * INNER + n * 4);
    float4 z4  = *(const float4*)(g_z + g * INNER + n * 4);
    float4 sk4 = *(const float4*)(skip + n * 4);
    float sz0 = z4.x / (1.f + __expf(-z4.x));
    float sz1 = z4.y / (1.f + __expf(-z4.y));
    float sz2 = z4.z / (1.f + __expf(-z4.z));
    float sz3 = z4.w / (1.f + __expf(-z4.w));
    float4 out = make_float4((hn0 + sk4.x * xc4.x) * sz0,
                             (hn1 + sk4.y * xc4.y) * sz1,
                             (hn2 + sk4.z * xc4.z) * sz2,
                             (hn3 + sk4.w * xc4.w) * sz3);
    *(float4*)(g_hstate + g * INNER + n * 4) = out;
}

// ---------------------------------------------------------------------------
// K_C: down-proj + residual only. 4 positions per block, 288 x 384 (R7 geom).
// ---------------------------------------------------------------------------
__global__ void kC(const float* __restrict__ x,
                   const float* __restrict__ b_down,
                   float* __restrict__ out) {
    __shared__ __align__(16) float hs[4 * INNER];
    __shared__ __align__(16) float part[4][4][100];
    const int g0 = blockIdx.x * 4;
    const int tid = threadIdx.x;            // 384
    // coalesced copy: 4*192 = 768 floats = 384 float2, one per thread
    ((float2*)hs)[tid] = ((const float2*)(g_hstate + g0 * INNER))[tid];
    __syncthreads();

    const int c = tid % 96;
    const int slice = tid / 96;             // 4 slices of 48
    const int f0 = slice * 48;
    float acc[4];
#pragma unroll
    for (int p = 0; p < 4; p++) acc[p] = 0.f;
    for (int f = 0; f < 48; f++) {
        float w = g_wdT[(f0 + f) * DIMC + c];
#pragma unroll
        for (int p = 0; p < 4; p++) acc[p] += w * hs[p * INNER + f0 + f];
    }
#pragma unroll
    for (int p = 0; p < 4; p++) part[p][slice][c] = acc[p];
    __syncthreads();

    const int b = g0 / SS, s0 = g0 % SS;
    {
        const int c2 = tid % 96, p2 = tid / 96;   // 384 outputs, 1/thread
        float v = part[p2][0][c2] + part[p2][1][c2] + part[p2][2][c2] + part[p2][3][c2]
                + b_down[c2];
        int gi = (b * DIMC + c2) * SS + s0 + p2;
        out[gi] = x[gi] + v;
    }
}

// ---------------------------------------------------------------------------
extern "C" void kernel_launch(void* const* d_in, const int* in_sizes, int n_in,
                              void* d_out, int out_size) {
    const float* x      = (const float*)d_in[0];
    const float* ln_g   = (const float*)d_in[1];
    const float* ln_b   = (const float*)d_in[2];
    const float* w_up   = (const float*)d_in[3];
    const float* b_up   = (const float*)d_in[4];
    const float* w_q    = (const float*)d_in[5];
    const float* b_q    = (const float*)d_in[6];
    const float* w_k    = (const float*)d_in[7];
    const float* b_k    = (const float*)d_in[8];
    const float* w_v    = (const float*)d_in[9];
    const float* b_v    = (const float*)d_in[10];
    const float* w_conv = (const float*)d_in[11];
    const float* b_conv = (const float*)d_in[12];
    const float* w_ig   = (const float*)d_in[13];
    const float* b_ig   = (const float*)d_in[14];
    const float* w_fg   = (const float*)d_in[15];
    const float* b_fg   = (const float*)d_in[16];
    const float* on_g   = (const float*)d_in[17];
    const float* on_b   = (const float*)d_in[18];
    const float* skip   = (const float*)d_in[19];
    const float* w_down = (const float*)d_in[20];
    const float* b_down = (const float*)d_in[21];
    float* out = (float*)d_out;

    const int ntrans = DIMC * 384 + F3 * 96 + INNER * DIMC;   // 110592
    kT<<<(ntrans + 255) / 256, 256>>>(w_up, w_ig, w_fg, w_down);
    kA<<<GTOT / 4, 384>>>(x, ln_g, ln_b, b_up, w_conv, b_conv,
                          w_q, b_q, w_k, b_k, w_v, b_v, b_ig, b_fg);
    kB<<<NBH, SS>>>(on_g, on_b, skip);
    kC<<<GTOT / 4, 384>>>(x, b_down, out);
}

// round 12
// speedup vs baseline: 2.0049x; 1.0016x over previous
#include <cuda_runtime.h>
#include <math.h>

#define BB 2
#define DIMC 96
#define INNER 192
#define NH 48
#define SS 576
#define GTOT (BB*SS)   // 1152
#define F3 (3*INNER)   // 576
#define NBH (BB*NH)    // 96

// Scratch (device globals; no allocation allowed)
__device__ float g_z[GTOT * INNER];
__device__ float g_xconv[GTOT * INNER];
__device__ float4 g_q4[NBH * SS];
__device__ float4 g_k4[NBH * SS];
__device__ float4 g_v4[NBH * SS];
__device__ float g_ig[NBH * SS];
__device__ float g_fg[NBH * SS];
__device__ float g_hstate[GTOT * INNER];   // (hnorm + skip*xconv)*silu(z)
__device__ float g_wupT[DIMC * 384];   // [c][o]
__device__ float g_wgT[F3 * 96];       // [f][2*jn + t], t=0:ig head jn, t=1:fg head jn
__device__ float g_wdT[INNER * DIMC];  // [f][c]

// ---------------------------------------------------------------------------
// kT: weight transposes; gate weights interleaved (ig,fg) per head
// ---------------------------------------------------------------------------
__global__ void kT(const float* __restrict__ w_up,
                   const float* __restrict__ w_ig,
                   const float* __restrict__ w_fg,
                   const float* __restrict__ w_down) {
    int i = blockIdx.x * 256 + threadIdx.x;
    if (i < DIMC * 384) {
        int c = i / 384, o = i % 384;
        g_wupT[c * 384 + o] = w_up[o * DIMC + c];
        return;
    }
    i -= DIMC * 384;
    if (i < F3 * 96) {
        int f = i / 96, j = i % 96;
        int col = (j < NH) ? (2 * j) : (2 * (j - NH) + 1);
        g_wgT[f * 96 + col] = (j < NH) ? w_ig[j * F3 + f] : w_fg[(j - NH) * F3 + f];
        return;
    }
    i -= F3 * 96;
    if (i < INNER * DIMC) {
        int f = i / DIMC, c = i % DIMC;
        g_wdT[f * DIMC + c] = w_down[c * INNER + f];
    }
}

// ---------------------------------------------------------------------------
// K_A: LN + up-proj (4 main + 3 halo) + causal conv + SiLU + qkv + gates.
// 288 blocks x 384 threads. LN'd input staged c-major (hT) for LDS.128.
// ---------------------------------------------------------------------------
__global__ void kA(const float* __restrict__ x,
                   const float* __restrict__ ln_g,
                   const float* __restrict__ ln_b,
                   const float* __restrict__ b_up,
                   const float* __restrict__ w_conv,
                   const float* __restrict__ b_conv,
                   const float* __restrict__ w_q, const float* __restrict__ b_q,
                   const float* __restrict__ w_k, const float* __restrict__ b_k,
                   const float* __restrict__ w_v, const float* __restrict__ b_v,
                   const float* __restrict__ b_ig, const float* __restrict__ b_fg) {
    __shared__ __align__(16) float hT[DIMC][8];     // LN'd input, c-major
    __shared__ float mu[7], iv[7];
    __shared__ __align__(16) float xim[7][INNER];   // x_mlstm half
    __shared__ __align__(16) float sq[4 * F3];      // q|k|v per main position
    __shared__ __align__(16) float part_i[4][8][48];
    __shared__ __align__(16) float part_f[4][8][48];
    const int g0 = blockIdx.x * 4;
    const int b = g0 / SS, sl0 = g0 % SS;   // blocks never straddle batches
    const int tid = threadIdx.x;            // 384
    const int wid = tid >> 5, lane = tid & 31;

    // ---- load x (7 rows: sloc = sl0-3+hp), zero-invalid; store c-major
    for (int i = tid; i < 7 * DIMC; i += 384) {
        int hp = i / DIMC, c = i % DIMC;
        int sloc = sl0 - 3 + hp;
        hT[c][hp] = (sloc >= 0) ? x[(b * DIMC + c) * SS + sloc] : 0.f;
    }
    __syncthreads();
    // ---- LN stats, warp per row
    if (wid < 7) {
        float sum = 0.f, sqv = 0.f;
        for (int c = lane; c < DIMC; c += 32) { float v = hT[c][wid]; sum += v; sqv += v * v; }
#pragma unroll
        for (int off = 16; off > 0; off >>= 1) {
            sum += __shfl_down_sync(0xffffffffu, sum, off);
            sqv += __shfl_down_sync(0xffffffffu, sqv, off);
        }
        if (lane == 0) {
            float m = sum * (1.f / DIMC);
            float var = sqv * (1.f / DIMC) - m * m;
            mu[wid] = m;
            iv[wid] = rsqrtf(var + 1e-5f);
        }
    }
    __syncthreads();
    for (int i = tid; i < 7 * DIMC; i += 384) {
        int hp = i / DIMC, c = i % DIMC;
        hT[c][hp] = (hT[c][hp] - mu[hp]) * iv[hp] * ln_g[c] + ln_b[c];
    }
    __syncthreads();

    // ---- up-proj: vectorized LDS.128 over the 7 positions per c
    if (tid < INNER) {
        const int o = tid;
        float acc[7];
        float bias = b_up[o];
#pragma unroll
        for (int p = 0; p < 7; p++) acc[p] = bias;
        for (int c = 0; c < DIMC; c++) {
            float w = g_wupT[c * 384 + o];
            float4 ha = *(const float4*)&hT[c][0];
            float4 hb = *(const float4*)&hT[c][4];
            acc[0] += w * ha.x; acc[1] += w * ha.y; acc[2] += w * ha.z;
            acc[3] += w * ha.w; acc[4] += w * hb.x; acc[5] += w * hb.y;
            acc[6] += w * hb.z;
        }
#pragma unroll
        for (int p = 0; p < 7; p++) xim[p][o] = acc[p];
    } else {
        const int o = tid;                   // 192..383 -> z channels
        float acc[4];
        float bias = b_up[o];
#pragma unroll
        for (int p = 0; p < 4; p++) acc[p] = bias;
        for (int c = 0; c < DIMC; c++) {
            float w = g_wupT[c * 384 + o];
            float4 ha = *(const float4*)&hT[c][0];
            float4 hb = *(const float4*)&hT[c][4];
            acc[0] += w * ha.w; acc[1] += w * hb.x;
            acc[2] += w * hb.y; acc[3] += w * hb.z;
        }
#pragma unroll
        for (int p = 0; p < 4; p++)
            g_z[(g0 + p) * INNER + (o - INNER)] = acc[p];
    }
    __syncthreads();

    // ---- conv + SiLU + qkv: thread = (p, n), 4*48 = 192 active
    if (tid < 192) {
        const int p = tid / NH, n = tid % NH;
        float xc[4];
#pragma unroll
        for (int d = 0; d < 4; d++) xc[d] = b_conv[n * 4 + d];
#pragma unroll
        for (int k = 0; k < 4; k++) {
            if (sl0 + p - 3 + k >= 0) {
                const float* xr = &xim[p + k][n * 4];
#pragma unroll
                for (int d = 0; d < 4; d++)
                    xc[d] += w_conv[(n * 4 + d) * 4 + k] * xr[d];
            }
        }
#pragma unroll
        for (int d = 0; d < 4; d++) {
            float sg = 1.f / (1.f + __expf(-xc[d]));
            xc[d] *= sg;
        }
        float xm0 = xim[p + 3][n * 4], xm1 = xim[p + 3][n * 4 + 1];
        float xm2 = xim[p + 3][n * 4 + 2], xm3 = xim[p + 3][n * 4 + 3];

        *(float4*)(g_xconv + (g0 + p) * INNER + n * 4) =
            make_float4(xc[0], xc[1], xc[2], xc[3]);

        float q[4], kk[4], v[4];
#pragma unroll
        for (int o = 0; o < 4; o++) {
            const float* wq = w_q + n * 16 + o * 4;
            q[o] = b_q[n * 4 + o] + wq[0]*xc[0] + wq[1]*xc[1] + wq[2]*xc[2] + wq[3]*xc[3];
            const float* wk = w_k + n * 16 + o * 4;
            kk[o] = b_k[n * 4 + o] + wk[0]*xc[0] + wk[1]*xc[1] + wk[2]*xc[2] + wk[3]*xc[3];
            const float* wv = w_v + n * 16 + o * 4;
            v[o] = b_v[n * 4 + o] + wv[0]*xm0 + wv[1]*xm1 + wv[2]*xm2 + wv[3]*xm3;
        }
        float4 qf = make_float4(q[0], q[1], q[2], q[3]);
        float4 kf = make_float4(kk[0], kk[1], kk[2], kk[3]);
        float4 vf = make_float4(v[0], v[1], v[2], v[3]);
        *(float4*)(sq + p * F3 + n * 4)             = qf;
        *(float4*)(sq + p * F3 + INNER + n * 4)     = kf;
        *(float4*)(sq + p * F3 + 2 * INNER + n * 4) = vf;
        int hidx = (b * NH + n) * SS + sl0 + p;
        g_q4[hidx] = qf;
        g_k4[hidx] = kf;
        g_v4[hidx] = vf;
    }
    __syncthreads();

    // ---- gates, ig/fg paired (interleaved weight float2): thread = (jn, slice)
    {
        const int jn = tid % 48;
        const int slice = tid / 48;          // 0..7
        const int f0 = slice * 72;
        float ai[4], af[4];
#pragma unroll
        for (int p = 0; p < 4; p++) { ai[p] = 0.f; af[p] = 0.f; }
        for (int f = 0; f < 72; f++) {
            float2 wv = *(const float2*)&g_wgT[(f0 + f) * 96 + 2 * jn];
#pragma unroll
            for (int p = 0; p < 4; p++) {
                float s = sq[p * F3 + f0 + f];
                ai[p] += wv.x * s;
                af[p] += wv.y * s;
            }
        }
#pragma unroll
        for (int p = 0; p < 4; p++) { part_i[p][slice][jn] = ai[p]; part_f[p][slice][jn] = af[p]; }
    }
    __syncthreads();
    {
        const int r2 = tid % 96, p2 = tid / 96;   // 384 outputs
        bool ii = r2 < NH;
        int n2 = ii ? r2 : r2 - NH;
        float v = 0.f;
#pragma unroll
        for (int sl = 0; sl < 8; sl++)
            v += ii ? part_i[p2][sl][n2] : part_f[p2][sl][n2];
        v += ii ? b_ig[n2] : b_fg[n2];
        float* dst = ii ? g_ig : g_fg;
        dst[(b * NH + n2) * SS + sl0 + p2] = v;
    }
}

// ---------------------------------------------------------------------------
// K_B: mLSTM linear-attention prefix sum + MH-norm + fused skip/z epilogue.
// One block per (b,head), 576 threads. (unchanged from R11)
// ---------------------------------------------------------------------------
__global__ void kB(const float* __restrict__ on_g,
                   const float* __restrict__ on_b,
                   const float* __restrict__ skip) {
    __shared__ float wsum[18], wmax[18], A_sh;
    __shared__ float wtot[18][20];
    __shared__ float epre[18][20];
    const int bh = blockIdx.x;
    const int b = bh / NH, n = bh % NH;
    const int s = threadIdx.x;               // 576
    const int wid = s >> 5, lane = s & 31;

    float fgv = g_fg[bh * SS + s];
    float igv = g_ig[bh * SS + s];
    float lf = (fgv > 0.f) ? -log1pf(__expf(-fgv)) : (fgv - log1pf(__expf(fgv)));
    float v = lf;
#pragma unroll
    for (int off = 1; off < 32; off <<= 1) {
        float nn = __shfl_up_sync(0xffffffffu, v, off);
        if (lane >= off) v += nn;
    }
    if (lane == 31) wsum[wid] = v;
    __syncthreads();
    float wex = 0.f;
    for (int ww = 0; ww < wid; ww++) wex += wsum[ww];
    const float cums = v + wex;
    const float a = igv - cums;
    float m = a;
#pragma unroll
    for (int off = 1; off < 32; off <<= 1) {
        float nn = __shfl_up_sync(0xffffffffu, m, off);
        if (lane >= off) m = fmaxf(m, nn);
    }
    if (lane == 31) wmax[wid] = m;
    __syncthreads();
    float wexm = -1e30f;
    for (int ww = 0; ww < wid; ww++) wexm = fmaxf(wexm, wmax[ww]);
    const float M = fmaxf(m, wexm);
    if (s == SS - 1) A_sh = M;
    __syncthreads();
    const float A = A_sh;
    const float E = 0.5f * __expf(a - A);

    float4 q4 = g_q4[bh * SS + s];
    float4 k4 = g_k4[bh * SS + s];
    float4 v4 = g_v4[bh * SS + s];
    float kv[4] = {k4.x, k4.y, k4.z, k4.w};
    float vv[4] = {v4.x, v4.y, v4.z, v4.w};
    float st[20];
#pragma unroll
    for (int j = 0; j < 4; j++) {
        float ek = E * kv[j];
        st[16 + j] = ek;
#pragma unroll
        for (int d = 0; d < 4; d++) st[j * 4 + d] = ek * vv[d];
    }
#pragma unroll
    for (int off = 1; off < 32; off <<= 1) {
        float tmp[20];
#pragma unroll
        for (int c = 0; c < 20; c++) tmp[c] = __shfl_up_sync(0xffffffffu, st[c], off);
        if (lane >= off) {
#pragma unroll
            for (int c = 0; c < 20; c++) st[c] += tmp[c];
        }
    }
    if (lane == 31) {
#pragma unroll
        for (int c = 0; c < 20; c++) wtot[wid][c] = st[c];
    }
    __syncthreads();
    if (wid == 0 && lane < 20) {
        float acc = 0.f;
        for (int ww = 0; ww < 18; ww++) { epre[ww][lane] = acc; acc += wtot[ww][lane]; }
    }
    __syncthreads();
#pragma unroll
    for (int c = 0; c < 20; c++) st[c] += epre[wid][c];

    float qv[4] = {q4.x, q4.y, q4.z, q4.w};
    float o[4] = {0.f, 0.f, 0.f, 0.f};
    float csum = 0.f;
#pragma unroll
    for (int j = 0; j < 4; j++) {
        csum += qv[j] * st[16 + j];
#pragma unroll
        for (int d = 0; d < 4; d++) o[d] += qv[j] * st[j * 4 + d];
    }
    float norm = fmaxf(fabsf(csum), __expf(-(cums + A)));
    float denom = norm + 1e-6f * __expf(M - A);
    float inv = 1.f / denom;
    float h0 = o[0] * inv, h1 = o[1] * inv, h2 = o[2] * inv, h3 = o[3] * inv;

    float mm = (h0 + h1 + h2 + h3) * 0.25f;
    float d0 = h0 - mm, d1 = h1 - mm, d2 = h2 - mm, d3 = h3 - mm;
    float var = (d0*d0 + d1*d1 + d2*d2 + d3*d3) * 0.25f;
    float r = rsqrtf(var + 1e-5f);
    float4 og = *(const float4*)(on_g + n * 4);
    float4 ob = *(const float4*)(on_b + n * 4);
    float hn0 = d0 * r * og.x + ob.x;
    float hn1 = d1 * r * og.y + ob.y;
    float hn2 = d2 * r * og.z + ob.z;
    float hn3 = d3 * r * og.w + ob.w;

    // fused epilogue: hstate = (hnorm + skip*xconv) * silu(z)
    const int g = b * SS + s;
    float4 xc4 = *(const float4*)(g_xconv + g * INNER + n * 4);
    float4 z4  = *(const float4*)(g_z + g * INNER + n * 4);
    float4 sk4 = *(const float4*)(skip + n * 4);
    float sz0 = z4.x / (1.f + __expf(-z4.x));
    float sz1 = z4.y / (1.f + __expf(-z4.y));
    float sz2 = z4.z / (1.f + __expf(-z4.z));
    float sz3 = z4.w / (1.f + __expf(-z4.w));
    float4 out = make_float4((hn0 + sk4.x * xc4.x) * sz0,
                             (hn1 + sk4.y * xc4.y) * sz1,
                             (hn2 + sk4.z * xc4.z) * sz2,
                             (hn3 + sk4.w * xc4.w) * sz3);
    *(float4*)(g_hstate + g * INNER + n * 4) = out;
}

// ---------------------------------------------------------------------------
// K_C: down-proj + residual. 288 blocks x 384 threads (proven geometry);
// hstate staged f-major (hsT) so the inner loop reads one LDS.128.
// ---------------------------------------------------------------------------
__global__ void kC(const float* __restrict__ x,
                   const float* __restrict__ b_down,
                   float* __restrict__ out) {
    __shared__ __align__(16) float hsT[INNER][4];    // [f][p]
    __shared__ __align__(16) float part[4][4][100];
    const int g0 = blockIdx.x * 4;
    const int tid = threadIdx.x;            // 384
    {
        // coalesced read: 768 floats = 384 float2; store transposed
        float2 hv = ((const float2*)(g_hstate + g0 * INNER))[tid];
        int i = tid * 2;
        int p = i / INNER, d = i % INNER;
        hsT[d][p] = hv.x;
        hsT[d + 1][p] = hv.y;
    }
    __syncthreads();

    const int c = tid % 96;
    const int slice = tid / 96;             // 4 slices of 48
    const int f0 = slice * 48;
    float acc[4];
#pragma unroll
    for (int p = 0; p < 4; p++) acc[p] = 0.f;
    for (int f = 0; f < 48; f++) {
        float w = g_wdT[(f0 + f) * DIMC + c];
        float4 hv = *(const float4*)&hsT[f0 + f][0];
        acc[0] += w * hv.x; acc[1] += w * hv.y;
        acc[2] += w * hv.z; acc[3] += w * hv.w;
    }
#pragma unroll
    for (int p = 0; p < 4; p++) part[p][slice][c] = acc[p];
    __syncthreads();

    const int b = g0 / SS, s0 = g0 % SS;
    {
        const int c2 = tid % 96, p2 = tid / 96;   // 384 outputs, 1/thread
        float v = part[p2][0][c2] + part[p2][1][c2] + part[p2][2][c2] + part[p2][3][c2]
                + b_down[c2];
        int gi = (b * DIMC + c2) * SS + s0 + p2;
        out[gi] = x[gi] + v;
    }
}

// ---------------------------------------------------------------------------
extern "C" void kernel_launch(void* const* d_in, const int* in_sizes, int n_in,
                              void* d_out, int out_size) {
    const float* x      = (const float*)d_in[0];
    const float* ln_g   = (const float*)d_in[1];
    const float* ln_b   = (const float*)d_in[2];
    const float* w_up   = (const float*)d_in[3];
    const float* b_up   = (const float*)d_in[4];
    const float* w_q    = (const float*)d_in[5];
    const float* b_q    = (const float*)d_in[6];
    const float* w_k    = (const float*)d_in[7];
    const float* b_k    = (const float*)d_in[8];
    const float* w_v    = (const float*)d_in[9];
    const float* b_v    = (const float*)d_in[10];
    const float* w_conv = (const float*)d_in[11];
    const float* b_conv = (const float*)d_in[12];
    const float* w_ig   = (const float*)d_in[13];
    const float* b_ig   = (const float*)d_in[14];
    const float* w_fg   = (const float*)d_in[15];
    const float* b_fg   = (const float*)d_in[16];
    const float* on_g   = (const float*)d_in[17];
    const float* on_b   = (const float*)d_in[18];
    const float* skip   = (const float*)d_in[19];
    const float* w_down = (const float*)d_in[20];
    const float* b_down = (const float*)d_in[21];
    float* out = (float*)d_out;

    const int ntrans = DIMC * 384 + F3 * 96 + INNER * DIMC;   // 110592
    kT<<<(ntrans + 255) / 256, 256>>>(w_up, w_ig, w_fg, w_down);
    kA<<<GTOT / 4, 384>>>(x, ln_g, ln_b, b_up, w_conv, b_conv,
                          w_q, b_q, w_k, b_k, w_v, b_v, b_ig, b_fg);
    kB<<<NBH, SS>>>(on_g, on_b, skip);
    kC<<<GTOT / 4, 384>>>(x, b_down, out);
}